// round 8
// baseline (speedup 1.0000x reference)
#include <cuda_runtime.h>

#define NN    4096

#define PED_SPEED   1.5f
#define ROBOT_SPEED 1.5f
#define K_ATTR      2.0f
#define ALPHA       10.0f
#define PED_RADIUS  0.3f
#define PED_MASS    60.0f
#define BETTA       0.71f
#define DT          0.4f
#define A_COST      4.0f
#define B_COST      1.2f
#define E_COST      0.001f
#define EPSF        1e-8f
#define LOG2E       1.4426950408889634f

#define C1C (-LOG2E / BETTA)
#define C0C ((2.0f * PED_RADIUS) * LOG2E / BETTA)

typedef unsigned long long u64;

// packed positions: element i = (-x[2i], -x[2i+1], -y[2i], -y[2i+1])
__device__ float4 g_pack[NN / 2];   // 32 KB, L1-resident
__device__ float  g_robo[4];        // r0x, r0y, PG

__device__ __forceinline__ float ex2_approx(float x) {
    float r;
    asm("ex2.approx.ftz.f32 %0, %1;" : "=f"(r) : "f"(x));
    return r;
}
__device__ __forceinline__ float rsqrt_approx(float x) {
    float r;
    asm("rsqrt.approx.ftz.f32 %0, %1;" : "=f"(r) : "f"(x));
    return r;
}

// ---- packed f32x2 helpers (fma-pipe FFMA2; ptxas won't auto-generate) ----
__device__ __forceinline__ u64 f2add(u64 a, u64 b) {
    u64 r; asm("add.rn.f32x2 %0, %1, %2;" : "=l"(r) : "l"(a), "l"(b)); return r;
}
__device__ __forceinline__ u64 f2mul(u64 a, u64 b) {
    u64 r; asm("mul.rn.f32x2 %0, %1, %2;" : "=l"(r) : "l"(a), "l"(b)); return r;
}
__device__ __forceinline__ u64 f2fma(u64 a, u64 b, u64 c) {
    u64 r; asm("fma.rn.f32x2 %0, %1, %2, %3;" : "=l"(r) : "l"(a), "l"(b), "l"(c)); return r;
}
__device__ __forceinline__ u64 fpack(float lo, float hi) {
    u64 r; asm("mov.b64 %0, {%1, %2};" : "=l"(r) : "f"(lo), "f"(hi)); return r;
}
__device__ __forceinline__ void funpack(u64 v, float& lo, float& hi) {
    asm("mov.b64 {%0, %1}, %2;" : "=f"(lo), "=f"(hi) : "l"(v));
}

// Prep: blocks 0..3 pack negated positions pairwise; block 4 computes the
// robot (row 0) propagated pose + PG once.
__global__ void __launch_bounds__(512) prep_kernel(
    const float4* __restrict__ state,
    const float2* __restrict__ goals,
    const float*  __restrict__ robot_init)
{
    const int tid = threadIdx.x;
    const int b   = blockIdx.x;

    if (b < 4) {
        int p = b * 512 + tid;            // pair index 0..2047
        float4 s0 = state[2 * p];
        float4 s1 = state[2 * p + 1];
        g_pack[p] = make_float4(-s0.x, -s1.x, -s0.y, -s1.y);
        return;
    }

    // ---- Robot row-0 force over all 4096 pairs (8 iters/thread) ----
    __shared__ float2 wsum[16];
    const float4 s0 = state[0];
    float fx = 0.0f, fy = 0.0f;
    #pragma unroll
    for (int k = 0; k < NN / 512; k++) {
        float4 q  = state[tid + k * 512];
        float dx  = s0.x - q.x;
        float dy  = s0.y - q.y;
        float s2  = fmaf(dx, dx, fmaf(dy, dy, EPSF));
        float rin = rsqrt_approx(s2);
        float m   = ex2_approx(fmaf(s2 * rin, C1C, C0C));
        float f   = m * rin;
        fx = fmaf(f, dx, fx);
        fy = fmaf(f, dy, fy);
    }
    #pragma unroll
    for (int sh = 16; sh > 0; sh >>= 1) {
        fx += __shfl_xor_sync(0xffffffffu, fx, sh);
        fy += __shfl_xor_sync(0xffffffffu, fy, sh);
    }
    if ((tid & 31) == 0) wsum[tid >> 5] = make_float2(fx, fy);
    __syncthreads();

    if (tid == 0) {
        float rx = 0.0f, ry = 0.0f;
        #pragma unroll
        for (int w = 0; w < 16; w++) { rx += wsum[w].x; ry += wsum[w].y; }
        rx *= ALPHA;
        ry *= ALPHA;

        float2 g0  = goals[0];
        float tgx  = g0.x - s0.x;
        float tgy  = g0.y - s0.y;
        float dist = sqrtf(fmaf(tgx, tgx, tgy * tgy));
        float einv = 1.0f / (dist + EPSF);
        float Fx   = rx + K_ATTR * (ROBOT_SPEED * tgx * einv - s0.z) * PED_MASS;
        float Fy   = ry + K_ATTR * (ROBOT_SPEED * tgy * einv - s0.w) * PED_MASS;

        float vnx   = fmaf(Fx, DT / PED_MASS, s0.z);
        float vny   = fmaf(Fy, DT / PED_MASS, s0.w);
        float speed = sqrtf(fmaf(vnx, vnx, vny * vny));
        float sc    = fminf(1.0f, PED_SPEED / (speed + EPSF));
        vnx *= sc;
        vny *= sc;
        float r0x = fmaf(vnx, DT, s0.x);
        float r0y = fmaf(vny, DT, s0.y);

        float rix = robot_init[0];
        float riy = robot_init[1];
        float gx  = g0.x - rix;
        float gy  = g0.y - riy;
        float PG  = (gx * (r0x - rix) + gy * (r0y - riy)) /
                    (sqrtf(fmaf(gx, gx, gy * gy)) + E_COST);
        g_robo[0] = r0x;
        g_robo[1] = r0y;
        g_robo[2] = PG;
    }
}

// Main: 1024 blocks x 128 threads; one warp per row. Packed f32x2 pair math,
// Newton-Raphson rsqrt (no MUFU), single EX2 MUFU per pair.
__global__ void __launch_bounds__(128) force_kernel(
    const float4* __restrict__ state,
    const float*  __restrict__ cost_in,
    const float4* __restrict__ stacked_in,
    const float2* __restrict__ goals,
    float4* __restrict__ out_state,
    float*  __restrict__ out_cost,
    float4* __restrict__ out_stacked)
{
    const int tid  = threadIdx.x;
    const int b    = blockIdx.x;
    const int row  = b * 4 + (tid >> 5);
    const int lane = tid & 31;

    // Stacked output copy for this block's 4 rows
    if (tid < 4) {
        int r = b * 4 + tid;
        out_stacked[r] = stacked_in[r];
    } else if (tid < 8) {
        int r = b * 4 + (tid - 4);
        out_stacked[NN + r] = state[r];
    }

    const float4 st = state[row];  // warp-uniform -> broadcast
    const float px = st.x, py = st.y;

    const u64 pxx  = fpack(px, px);
    const u64 pyy  = fpack(py, py);
    const u64 eps2 = fpack(EPSF, EPSF);
    const u64 c1p  = fpack(C1C, C1C);
    const u64 c0p  = fpack(C0C, C0C);
    const u64 mh2  = fpack(-0.5f, -0.5f);
    const u64 c15  = fpack(1.5f, 1.5f);

    u64 accx = fpack(0.0f, 0.0f);
    u64 accy = fpack(0.0f, 0.0f);

    const longlong2* __restrict__ gp = reinterpret_cast<const longlong2*>(g_pack);

    // 64 counted iters, 2 pairs each. Self-pair contributes exactly 0
    // (dx=dy=0 exact since prep stores -pos; f finite via EPS).
    #pragma unroll 8
    for (int k = 0; k < NN / 64; k++) {
        longlong2 q = gp[lane + k * 32];   // LDG.128: (.x = -x pair, .y = -y pair)
        u64 nx2 = (u64)q.x;
        u64 ny2 = (u64)q.y;

        u64 dx2 = f2add(pxx, nx2);                    // (dx0, dx1)
        u64 dy2 = f2add(pyy, ny2);                    // (dy0, dy1)
        u64 s2  = f2fma(dx2, dx2, f2fma(dy2, dy2, eps2));

        // NR rsqrt from bit-hack seed, 2 iterations (rel err ~5e-6)
        float s2lo, s2hi;
        funpack(s2, s2lo, s2hi);
        float y0 = __uint_as_float(0x5f3759dfu - (__float_as_uint(s2lo) >> 1));
        float y1 = __uint_as_float(0x5f3759dfu - (__float_as_uint(s2hi) >> 1));
        u64 y2   = fpack(y0, y1);
        u64 nh   = f2mul(s2, mh2);                    // -0.5*s2
        u64 t    = f2mul(y2, y2);
        y2 = f2mul(y2, f2fma(nh, t, c15));
        t  = f2mul(y2, y2);
        y2 = f2mul(y2, f2fma(nh, t, c15));            // rin = 1/sqrt(s2)

        u64 d2   = f2mul(s2, y2);                     // d = s2*rin
        u64 arg  = f2fma(d2, c1p, c0p);
        float a0, a1;
        funpack(arg, a0, a1);
        u64 m2 = fpack(ex2_approx(a0), ex2_approx(a1));
        u64 f2 = f2mul(m2, y2);                       // m * rin
        accx = f2fma(f2, dx2, accx);
        accy = f2fma(f2, dy2, accy);
    }

    float fx0, fx1, fy0, fy1;
    funpack(accx, fx0, fx1);
    funpack(accy, fy0, fy1);
    float fx = fx0 + fx1;
    float fy = fy0 + fy1;

    #pragma unroll
    for (int sh = 16; sh > 0; sh >>= 1) {
        fx += __shfl_xor_sync(0xffffffffu, fx, sh);
        fy += __shfl_xor_sync(0xffffffffu, fy, sh);
    }

    // Lane 0: attraction + pose propagation + cost for own row
    if (lane == 0) {
        fx *= ALPHA;
        fy *= ALPHA;

        float2 g   = goals[row];
        float tgx  = g.x - px;
        float tgy  = g.y - py;
        float dist = sqrtf(fmaf(tgx, tgx, tgy * tgy));
        float einv = 1.0f / (dist + EPSF);
        float ds   = (row == 0) ? ROBOT_SPEED : PED_SPEED;
        float Fx   = fx + K_ATTR * (ds * tgx * einv - st.z) * PED_MASS;
        float Fy   = fy + K_ATTR * (ds * tgy * einv - st.w) * PED_MASS;

        float vnx   = fmaf(Fx, DT / PED_MASS, st.z);
        float vny   = fmaf(Fy, DT / PED_MASS, st.w);
        float speed = sqrtf(fmaf(vnx, vnx, vny * vny));
        float sc    = fminf(1.0f, PED_SPEED / (speed + EPSF));
        vnx *= sc;
        vny *= sc;
        float pnx = fmaf(vnx, DT, px);
        float pny = fmaf(vny, DT, py);
        out_state[row] = make_float4(pnx, pny, vnx, vny);

        // Cost (robot pose + PG precomputed by prep kernel)
        float r0x = g_robo[0], r0y = g_robo[1], PG = g_robo[2];
        float ddx = pnx - r0x;
        float ddy = pny - r0y;
        float dr  = sqrtf(fmaf(ddx, ddx, fmaf(ddy, ddy, E_COST)));
        float blame = (row == 0) ? 0.0f : ex2_approx(-dr * (LOG2E / B_COST));
        out_cost[row] = cost_in[row] + (-A_COST * PG + blame);
    }
}

extern "C" void kernel_launch(void* const* d_in, const int* in_sizes, int n_in,
                              void* d_out, int out_size)
{
    const float4* state   = (const float4*)d_in[0];
    const float*  cost    = (const float*)d_in[1];
    const float4* stacked = (const float4*)d_in[2];
    const float2* goals   = (const float2*)d_in[3];
    const float*  rinit   = (const float*)d_in[4];

    float*  out         = (float*)d_out;
    float4* out_state   = (float4*)out;            // [0, 4N)
    float*  out_cost    = out + 4 * NN;            // [4N, 5N)
    float4* out_stacked = (float4*)(out + 5 * NN); // [5N, 13N)

    prep_kernel<<<5, 512>>>(state, goals, rinit);
    force_kernel<<<NN / 4, 128>>>(state, cost, stacked, goals,
                                  out_state, out_cost, out_stacked);
}

// round 9
// speedup vs baseline: 1.2765x; 1.2765x over previous
#include <cuda_runtime.h>

#define NN    4096

#define PED_SPEED   1.5f
#define ROBOT_SPEED 1.5f
#define K_ATTR      2.0f
#define ALPHA       10.0f
#define PED_RADIUS  0.3f
#define PED_MASS    60.0f
#define BETTA       0.71f
#define DT          0.4f
#define A_COST      4.0f
#define B_COST      1.2f
#define E_COST      0.001f
#define EPSF        1e-8f
#define LOG2E       1.4426950408889634f

#define C1C (-LOG2E / BETTA)
#define C0C ((2.0f * PED_RADIUS) * LOG2E / BETTA)

typedef unsigned long long u64;

// packed positions: element i = (-x[2i], -x[2i+1], -y[2i], -y[2i+1])
__device__ float4 g_pack[NN / 2];   // 32 KB, L1-resident
__device__ float  g_robo[4];        // r0x, r0y, PG

__device__ __forceinline__ float ex2_approx(float x) {
    float r;
    asm("ex2.approx.ftz.f32 %0, %1;" : "=f"(r) : "f"(x));
    return r;
}
__device__ __forceinline__ float rsqrt_approx(float x) {
    float r;
    asm("rsqrt.approx.ftz.f32 %0, %1;" : "=f"(r) : "f"(x));
    return r;
}

// ---- packed f32x2 helpers (fma-pipe FFMA2) ----
__device__ __forceinline__ u64 f2add(u64 a, u64 b) {
    u64 r; asm("add.rn.f32x2 %0, %1, %2;" : "=l"(r) : "l"(a), "l"(b)); return r;
}
__device__ __forceinline__ u64 f2mul(u64 a, u64 b) {
    u64 r; asm("mul.rn.f32x2 %0, %1, %2;" : "=l"(r) : "l"(a), "l"(b)); return r;
}
__device__ __forceinline__ u64 f2fma(u64 a, u64 b, u64 c) {
    u64 r; asm("fma.rn.f32x2 %0, %1, %2, %3;" : "=l"(r) : "l"(a), "l"(b), "l"(c)); return r;
}
__device__ __forceinline__ u64 fpack(float lo, float hi) {
    u64 r; asm("mov.b64 %0, {%1, %2};" : "=l"(r) : "f"(lo), "f"(hi)); return r;
}
__device__ __forceinline__ void funpack(u64 v, float& lo, float& hi) {
    asm("mov.b64 {%0, %1}, %2;" : "=f"(lo), "=f"(hi) : "l"(v));
}

// Prep: blocks 0..3 pack negated positions pairwise; block 4 computes the
// robot (row 0) propagated pose + PG once.
__global__ void __launch_bounds__(512) prep_kernel(
    const float4* __restrict__ state,
    const float2* __restrict__ goals,
    const float*  __restrict__ robot_init)
{
    const int tid = threadIdx.x;
    const int b   = blockIdx.x;

    if (b < 4) {
        int p = b * 512 + tid;            // pair index 0..2047
        float4 s0 = state[2 * p];
        float4 s1 = state[2 * p + 1];
        g_pack[p] = make_float4(-s0.x, -s1.x, -s0.y, -s1.y);
        return;
    }

    // ---- Robot row-0 force over all 4096 pairs (8 iters/thread) ----
    __shared__ float2 wsum[16];
    const float4 s0 = state[0];
    float fx = 0.0f, fy = 0.0f;
    #pragma unroll
    for (int k = 0; k < NN / 512; k++) {
        float4 q  = state[tid + k * 512];
        float dx  = s0.x - q.x;
        float dy  = s0.y - q.y;
        float s2  = fmaf(dx, dx, fmaf(dy, dy, EPSF));
        float rin = rsqrt_approx(s2);
        float m   = ex2_approx(fmaf(s2 * rin, C1C, C0C));
        float f   = m * rin;
        fx = fmaf(f, dx, fx);
        fy = fmaf(f, dy, fy);
    }
    #pragma unroll
    for (int sh = 16; sh > 0; sh >>= 1) {
        fx += __shfl_xor_sync(0xffffffffu, fx, sh);
        fy += __shfl_xor_sync(0xffffffffu, fy, sh);
    }
    if ((tid & 31) == 0) wsum[tid >> 5] = make_float2(fx, fy);
    __syncthreads();

    if (tid == 0) {
        float rx = 0.0f, ry = 0.0f;
        #pragma unroll
        for (int w = 0; w < 16; w++) { rx += wsum[w].x; ry += wsum[w].y; }
        rx *= ALPHA;
        ry *= ALPHA;

        float2 g0  = goals[0];
        float tgx  = g0.x - s0.x;
        float tgy  = g0.y - s0.y;
        float dist = sqrtf(fmaf(tgx, tgx, tgy * tgy));
        float einv = 1.0f / (dist + EPSF);
        float Fx   = rx + K_ATTR * (ROBOT_SPEED * tgx * einv - s0.z) * PED_MASS;
        float Fy   = ry + K_ATTR * (ROBOT_SPEED * tgy * einv - s0.w) * PED_MASS;

        float vnx   = fmaf(Fx, DT / PED_MASS, s0.z);
        float vny   = fmaf(Fy, DT / PED_MASS, s0.w);
        float speed = sqrtf(fmaf(vnx, vnx, vny * vny));
        float sc    = fminf(1.0f, PED_SPEED / (speed + EPSF));
        vnx *= sc;
        vny *= sc;
        float r0x = fmaf(vnx, DT, s0.x);
        float r0y = fmaf(vny, DT, s0.y);

        float rix = robot_init[0];
        float riy = robot_init[1];
        float gx  = g0.x - rix;
        float gy  = g0.y - riy;
        float PG  = (gx * (r0x - rix) + gy * (r0y - riy)) /
                    (sqrtf(fmaf(gx, gx, gy * gy)) + E_COST);
        g_robo[0] = r0x;
        g_robo[1] = r0y;
        g_robo[2] = PG;
    }
}

// Main: 1024 blocks x 256 threads; TWO warps per row (8192 warps total,
// ~55 warps/SM) to cover latency. Packed f32x2 math + MUFU rsqrt.
__global__ void __launch_bounds__(256, 7) force_kernel(
    const float4* __restrict__ state,
    const float*  __restrict__ cost_in,
    const float4* __restrict__ stacked_in,
    const float2* __restrict__ goals,
    float4* __restrict__ out_state,
    float*  __restrict__ out_cost,
    float4* __restrict__ out_stacked)
{
    __shared__ float2 swred[8];   // per-warp partial sums

    const int tid   = threadIdx.x;
    const int b     = blockIdx.x;
    const int warp  = tid >> 5;
    const int lane  = tid & 31;
    const int rloc  = warp >> 1;          // local row 0..3
    const int half  = warp & 1;           // which half of the pair list
    const int row   = b * 4 + rloc;

    // Stacked output copy for this block's 4 rows
    if (tid < 4) {
        int r = b * 4 + tid;
        out_stacked[r] = stacked_in[r];
    } else if (tid < 8) {
        int r = b * 4 + (tid - 4);
        out_stacked[NN + r] = state[r];
    }

    const float4 st = state[row];  // warp-uniform -> broadcast
    const float px = st.x, py = st.y;

    const u64 pxx  = fpack(px, px);
    const u64 pyy  = fpack(py, py);
    const u64 eps2 = fpack(EPSF, EPSF);
    const u64 c1p  = fpack(C1C, C1C);
    const u64 c0p  = fpack(C0C, C0C);

    u64 accx = fpack(0.0f, 0.0f);
    u64 accy = fpack(0.0f, 0.0f);

    const longlong2* __restrict__ gp = reinterpret_cast<const longlong2*>(g_pack);

    // 32 counted iters per warp, 2 pairs each (2 warps cover the row).
    // Self-pair contributes exactly 0 (dx=dy=0 exact; f finite via EPS).
    #pragma unroll 8
    for (int k = 0; k < NN / 128; k++) {
        longlong2 q = gp[half * 32 + lane + k * 64];  // LDG.128
        u64 nx2 = (u64)q.x;
        u64 ny2 = (u64)q.y;

        u64 dx2 = f2add(pxx, nx2);                    // (dx0, dx1)
        u64 dy2 = f2add(pyy, ny2);                    // (dy0, dy1)
        u64 s2  = f2fma(dx2, dx2, f2fma(dy2, dy2, eps2));

        float s2lo, s2hi;
        funpack(s2, s2lo, s2hi);
        u64 y2 = fpack(rsqrt_approx(s2lo), rsqrt_approx(s2hi));

        u64 d2  = f2mul(s2, y2);                      // d = s2*rin
        u64 arg = f2fma(d2, c1p, c0p);
        float a0, a1;
        funpack(arg, a0, a1);
        u64 m2 = fpack(ex2_approx(a0), ex2_approx(a1));
        u64 f2 = f2mul(m2, y2);                       // m * rin
        accx = f2fma(f2, dx2, accx);
        accy = f2fma(f2, dy2, accy);
    }

    float fx0, fx1, fy0, fy1;
    funpack(accx, fx0, fx1);
    funpack(accy, fy0, fy1);
    float fx = fx0 + fx1;
    float fy = fy0 + fy1;

    #pragma unroll
    for (int sh = 16; sh > 0; sh >>= 1) {
        fx += __shfl_xor_sync(0xffffffffu, fx, sh);
        fy += __shfl_xor_sync(0xffffffffu, fy, sh);
    }
    if (lane == 0) swred[warp] = make_float2(fx, fy);
    __syncthreads();

    // 4 epilogue threads: combine warp pairs, propagate pose, cost
    if (tid < 4) {
        int r = b * 4 + tid;
        float2 h0 = swred[2 * tid];
        float2 h1 = swred[2 * tid + 1];
        float Fx = (h0.x + h1.x) * ALPHA;
        float Fy = (h0.y + h1.y) * ALPHA;

        float4 sr = state[r];
        float2 g  = goals[r];
        float tgx  = g.x - sr.x;
        float tgy  = g.y - sr.y;
        float dist = sqrtf(fmaf(tgx, tgx, tgy * tgy));
        float einv = 1.0f / (dist + EPSF);
        float ds   = (r == 0) ? ROBOT_SPEED : PED_SPEED;
        Fx += K_ATTR * (ds * tgx * einv - sr.z) * PED_MASS;
        Fy += K_ATTR * (ds * tgy * einv - sr.w) * PED_MASS;

        float vnx   = fmaf(Fx, DT / PED_MASS, sr.z);
        float vny   = fmaf(Fy, DT / PED_MASS, sr.w);
        float speed = sqrtf(fmaf(vnx, vnx, vny * vny));
        float sc    = fminf(1.0f, PED_SPEED / (speed + EPSF));
        vnx *= sc;
        vny *= sc;
        float pnx = fmaf(vnx, DT, sr.x);
        float pny = fmaf(vny, DT, sr.y);
        out_state[r] = make_float4(pnx, pny, vnx, vny);

        // Cost (robot pose + PG precomputed by prep kernel)
        float r0x = g_robo[0], r0y = g_robo[1], PG = g_robo[2];
        float ddx = pnx - r0x;
        float ddy = pny - r0y;
        float dr  = sqrtf(fmaf(ddx, ddx, fmaf(ddy, ddy, E_COST)));
        float blame = (r == 0) ? 0.0f : ex2_approx(-dr * (LOG2E / B_COST));
        out_cost[r] = cost_in[r] + (-A_COST * PG + blame);
    }
}

extern "C" void kernel_launch(void* const* d_in, const int* in_sizes, int n_in,
                              void* d_out, int out_size)
{
    const float4* state   = (const float4*)d_in[0];
    const float*  cost    = (const float*)d_in[1];
    const float4* stacked = (const float4*)d_in[2];
    const float2* goals   = (const float2*)d_in[3];
    const float*  rinit   = (const float*)d_in[4];

    float*  out         = (float*)d_out;
    float4* out_state   = (float4*)out;            // [0, 4N)
    float*  out_cost    = out + 4 * NN;            // [4N, 5N)
    float4* out_stacked = (float4*)(out + 5 * NN); // [5N, 13N)

    prep_kernel<<<5, 512>>>(state, goals, rinit);
    force_kernel<<<NN / 4, 256>>>(state, cost, stacked, goals,
                                  out_state, out_cost, out_stacked);
}